// round 10
// baseline (speedup 1.0000x reference)
#include <cuda_runtime.h>
#include <cuda_fp16.h>
#include <cstdint>

// Problem shape (fixed by dataset)
#define M_TOKENS 16384
#define K_DIM    2048
#define N_DIM    2048
#define EPS      1e-7f

// GEMM tiling: 128x128 CTA tile, K-chunk of 64 fp16 (128 B) per stage
#define BM 128
#define BN 128
#define NSTAGE 3
#define SROW 144                       // 128B payload + 16B pad (conflict-free)
#define STAGE_B ((BM + BN) * SROW)     // 36864 bytes
#define NKT 32                         // 2048 / 64

// Scratch (device globals)
__device__ __half g_qh[(size_t)M_TOKENS * K_DIM];  // fp16 activations (exact int8 values)
__device__ __half g_wh[(size_t)N_DIM * K_DIM];     // fp16 weights
__device__ float  g_scales[M_TOKENS];

// ---------------------------------------------------------------------------
// Kernel 0: pack int32-marshalled weights to fp16 (exact, |w| <= 127).
// ---------------------------------------------------------------------------
__global__ __launch_bounds__(256) void pack_w_kernel(const int* __restrict__ w32) {
    const int idx = blockIdx.x * blockDim.x + threadIdx.x;
    int4 v = reinterpret_cast<const int4*>(w32)[idx];
    __half2 h0 = __halves2half2(__int2half_rn(v.x), __int2half_rn(v.y));
    __half2 h1 = __halves2half2(__int2half_rn(v.z), __int2half_rn(v.w));
    uint2 hp = make_uint2(*(uint32_t*)&h0, *(uint32_t*)&h1);
    reinterpret_cast<uint2*>(g_wh)[idx] = hp;
}

// ---------------------------------------------------------------------------
// Kernel 1: per-token dynamic int8 quantization -> fp16 values (exact).
// ---------------------------------------------------------------------------
__global__ __launch_bounds__(256) void quant_kernel(const float* __restrict__ x) {
    const int token = blockIdx.x;
    const int tid = threadIdx.x;
    const int lane = tid & 31;
    const int warp = tid >> 5;

    const float4* xr = reinterpret_cast<const float4*>(x + (size_t)token * K_DIM);
    float4 v0 = xr[tid * 2 + 0];
    float4 v1 = xr[tid * 2 + 1];

    float m = fabsf(v0.x);
    m = fmaxf(m, fabsf(v0.y)); m = fmaxf(m, fabsf(v0.z)); m = fmaxf(m, fabsf(v0.w));
    m = fmaxf(m, fabsf(v1.x)); m = fmaxf(m, fabsf(v1.y));
    m = fmaxf(m, fabsf(v1.z)); m = fmaxf(m, fabsf(v1.w));

    #pragma unroll
    for (int off = 16; off > 0; off >>= 1)
        m = fmaxf(m, __shfl_xor_sync(0xFFFFFFFFu, m, off));

    __shared__ float wmax[8];
    if (lane == 0) wmax[warp] = m;
    __syncthreads();
    if (warp == 0) {
        float t = (lane < 8) ? wmax[lane] : 0.0f;
        #pragma unroll
        for (int off = 4; off > 0; off >>= 1)
            t = fmaxf(t, __shfl_xor_sync(0xFFFFFFFFu, t, off));
        if (lane == 0) wmax[0] = t;
    }
    __syncthreads();
    const float absmax = wmax[0];
    const float scale = fmaxf(absmax, EPS) / 127.0f;

    if (tid == 0) g_scales[token] = scale;

    const float inv = 1.0f / scale;
    float vals[8] = {v0.x, v0.y, v0.z, v0.w, v1.x, v1.y, v1.z, v1.w};
    int qv[8];
    #pragma unroll
    for (int i = 0; i < 8; i++) {
        float q = rintf(vals[i] * inv);
        q = fminf(fmaxf(q, -128.0f), 127.0f);
        qv[i] = (int)q;
    }
    uint4 hq;
    __half2 h;
    h = __halves2half2(__int2half_rn(qv[0]), __int2half_rn(qv[1])); hq.x = *(uint32_t*)&h;
    h = __halves2half2(__int2half_rn(qv[2]), __int2half_rn(qv[3])); hq.y = *(uint32_t*)&h;
    h = __halves2half2(__int2half_rn(qv[4]), __int2half_rn(qv[5])); hq.z = *(uint32_t*)&h;
    h = __halves2half2(__int2half_rn(qv[6]), __int2half_rn(qv[7])); hq.w = *(uint32_t*)&h;
    *reinterpret_cast<uint4*>(g_qh + (size_t)token * K_DIM + tid * 8) = hq;
}

// ---------------------------------------------------------------------------
// Kernel 2: fp16 HMMA GEMM. 128x128 tile, 3-stage cp.async, 128B K-chunks,
// ldmatrix with explicit cross-ks fragment double buffering, 2 CTAs/SM.
// Launched twice with different m_base (profiling + no perf cost).
// ---------------------------------------------------------------------------
__device__ __forceinline__ void cp16s(uint32_t saddr, const void* g) {
    asm volatile("cp.async.cg.shared.global [%0], [%1], 16;\n" :: "r"(saddr), "l"(g));
}
__device__ __forceinline__ void ldsm4(uint32_t& r0, uint32_t& r1, uint32_t& r2, uint32_t& r3,
                                      uint32_t addr) {
    asm volatile("ldmatrix.sync.aligned.m8n8.x4.shared.b16 {%0,%1,%2,%3}, [%4];"
                 : "=r"(r0), "=r"(r1), "=r"(r2), "=r"(r3) : "r"(addr));
}

__global__ __launch_bounds__(256, 2) void gemm_f16_kernel(const float* __restrict__ w_scale,
                                                          const float* __restrict__ bias,
                                                          float* __restrict__ out,
                                                          int m_base) {
    extern __shared__ char smem[];
    const uint32_t sbase = (uint32_t)__cvta_generic_to_shared(smem);

    const int tid = threadIdx.x;
    const int lane = tid & 31;
    const int warp = tid >> 5;
    const int warpM = warp >> 2;   // 0..1 (64 rows)
    const int warpN = warp & 3;    // 0..3 (32 cols)
    const int g = lane >> 2;
    const int tg = lane & 3;

    const int m0 = m_base + blockIdx.y * BM;
    const int n0 = blockIdx.x * BN;

    const __half* Ag = g_qh + (size_t)m0 * K_DIM;
    const __half* Bg = g_wh + (size_t)n0 * K_DIM;

    float acc[4][4][4];
    #pragma unroll
    for (int mi = 0; mi < 4; mi++)
        #pragma unroll
        for (int ni = 0; ni < 4; ni++)
            #pragma unroll
            for (int r = 0; r < 4; r++) acc[mi][ni][r] = 0.0f;

    // Per stage: 256 rows x 128 B = 2048 x 16B segments, 8 per thread.
    auto issue_stage = [&](int stage, int kb) {    // kb = K byte offset
        const uint32_t base = sbase + stage * STAGE_B;
        #pragma unroll
        for (int it = 0; it < 8; it++) {
            int c = tid + it * 256;                // 0..2047
            int r = c >> 3, kc = (c & 7) * 16;     // row 0..255, byte col 0..112
            const char* src = (r < BM)
                ? (const char*)(Ag + (size_t)r * K_DIM) + kb + kc
                : (const char*)(Bg + (size_t)(r - BM) * K_DIM) + kb + kc;
            cp16s(base + r * SROW + kc, src);
        }
    };

    #pragma unroll
    for (int s = 0; s < NSTAGE - 1; s++) {
        issue_stage(s, s * 128);
        asm volatile("cp.async.commit_group;\n");
    }

    // ldmatrix lane-address components (validated layout)
    const int aRow = warpM * 64 + (lane & 7) + ((lane >> 3) & 1) * 8;   // + mi*16
    const int aKof = (lane >> 4) * 16;                                  // + ks*32
    const int bRow = BM + warpN * 32 + (lane >> 4) * 8 + (lane & 7);    // + j2*16
    const int bKof = ((lane >> 3) & 1) * 16;                            // + ks*32

    uint32_t afr[2][4][4];
    uint32_t bfr[2][4][2];

    auto load_frags = [&](int buf, uint32_t base, int ks) {
        const int k0 = ks * 32;
        #pragma unroll
        for (int mi = 0; mi < 4; mi++)
            ldsm4(afr[buf][mi][0], afr[buf][mi][1], afr[buf][mi][2], afr[buf][mi][3],
                  base + (aRow + mi * 16) * SROW + k0 + aKof);
        #pragma unroll
        for (int j2 = 0; j2 < 2; j2++) {
            uint32_t b0, b1, b2, b3;
            ldsm4(b0, b1, b2, b3, base + (bRow + j2 * 16) * SROW + k0 + bKof);
            bfr[buf][2 * j2][0] = b0; bfr[buf][2 * j2][1] = b1;
            bfr[buf][2 * j2 + 1][0] = b2; bfr[buf][2 * j2 + 1][1] = b3;
        }
    };
    auto do_mma = [&](int buf) {
        #pragma unroll
        for (int mi = 0; mi < 4; mi++)
            #pragma unroll
            for (int ni = 0; ni < 4; ni++) {
                asm volatile(
                    "mma.sync.aligned.m16n8k16.row.col.f32.f16.f16.f32 "
                    "{%0,%1,%2,%3}, {%4,%5,%6,%7}, {%8,%9}, {%0,%1,%2,%3};\n"
                    : "+f"(acc[mi][ni][0]), "+f"(acc[mi][ni][1]),
                      "+f"(acc[mi][ni][2]), "+f"(acc[mi][ni][3])
                    : "r"(afr[buf][mi][0]), "r"(afr[buf][mi][1]),
                      "r"(afr[buf][mi][2]), "r"(afr[buf][mi][3]),
                      "r"(bfr[buf][ni][0]), "r"(bfr[buf][ni][1]));
            }
    };

    int stage = 0;
    for (int kt = 0; kt < NKT; kt++) {
        asm volatile("cp.async.wait_group %0;\n" :: "n"(NSTAGE - 2));
        __syncthreads();

        const int pf = kt + NSTAGE - 1;
        int pstage = stage + NSTAGE - 1; if (pstage >= NSTAGE) pstage -= NSTAGE;
        if (pf < NKT) issue_stage(pstage, pf * 128);
        asm volatile("cp.async.commit_group;\n");

        const uint32_t base = sbase + stage * STAGE_B;

        // ks pipeline: prefetch ks+1 fragments before issuing ks MMAs
        load_frags(0, base, 0);
        #pragma unroll
        for (int ks = 0; ks < 4; ks++) {
            const int cur = ks & 1;
            if (ks < 3) load_frags(cur ^ 1, base, ks + 1);
            do_mma(cur);
        }
        if (++stage == NSTAGE) stage = 0;
    }

    // Epilogue: dequant + bias, round through fp16, store fp32 (validated).
    #pragma unroll
    for (int mi = 0; mi < 4; mi++) {
        const int r0 = m0 + warpM * 64 + mi * 16 + g;
        const float s0 = g_scales[r0];
        const float s1 = g_scales[r0 + 8];
        #pragma unroll
        for (int ni = 0; ni < 4; ni++) {
            const int c = n0 + warpN * 32 + ni * 8 + tg * 2;
            const float w0 = w_scale[c], w1 = w_scale[c + 1];
            const float b0 = bias[c],    b1 = bias[c + 1];
            float2 o0, o1;
            o0.x = __half2float(__float2half_rn(acc[mi][ni][0] * s0 * w0 + b0));
            o0.y = __half2float(__float2half_rn(acc[mi][ni][1] * s0 * w1 + b1));
            o1.x = __half2float(__float2half_rn(acc[mi][ni][2] * s1 * w0 + b0));
            o1.y = __half2float(__float2half_rn(acc[mi][ni][3] * s1 * w1 + b1));
            *reinterpret_cast<float2*>(out + (size_t)r0 * N_DIM + c) = o0;
            *reinterpret_cast<float2*>(out + (size_t)(r0 + 8) * N_DIM + c) = o1;
        }
    }
}

extern "C" void kernel_launch(void* const* d_in, const int* in_sizes, int n_in,
                              void* d_out, int out_size) {
    const float* x       = (const float*)d_in[0];
    const int*   weight  = (const int*)d_in[1];   // int8 marshalled as int32
    const float* w_scale = (const float*)d_in[2];
    const float* bias    = (const float*)d_in[3];
    float* out = (float*)d_out;

    pack_w_kernel<<<(N_DIM * K_DIM / 4) / 256, 256>>>(weight);
    quant_kernel<<<M_TOKENS, 256>>>(x);

    const int smem_bytes = NSTAGE * STAGE_B;  // 110592
    cudaFuncSetAttribute(gemm_f16_kernel, cudaFuncAttributeMaxDynamicSharedMemorySize, smem_bytes);
    // Two half-M launches (perf-neutral; steers ncu's fixed -s 5 -c 1 onto a GEMM)
    dim3 grid(N_DIM / BN, M_TOKENS / BM / 2);   // (16, 64)
    gemm_f16_kernel<<<grid, 256, smem_bytes>>>(w_scale, bias, out, 0);
    gemm_f16_kernel<<<grid, 256, smem_bytes>>>(w_scale, bias, out, M_TOKENS / 2);
}

// round 11
// speedup vs baseline: 1.2922x; 1.2922x over previous
#include <cuda_runtime.h>
#include <cuda.h>
#include <cuda_fp16.h>
#include <cstdint>

// Problem shape (fixed by dataset)
#define M_TOKENS 16384
#define K_DIM    2048
#define N_DIM    2048
#define EPS      1e-7f

// GEMM tiling: 128x128 CTA tile, K-chunk = 64 fp16 = 128 B per stage
#define BM 128
#define BN 128
#define NSTAGE 3
#define NKT 32
#define STAGE_B 32768                 // A 16KB + B 16KB, SW128-swizzled, pitch 128
#define SMEM_BARS (NSTAGE * STAGE_B)  // 98304
#define FULL_BAR(s)  (SMEM_BARS + (s) * 8)
#define EMPTY_BAR(s) (SMEM_BARS + 32 + (s) * 8)
#define SMEM_TOTAL (SMEM_BARS + 64)

// Scratch (device globals)
__device__ __align__(1024) __half g_qh[(size_t)M_TOKENS * K_DIM];  // fp16 activations
__device__ __align__(1024) __half g_wh[(size_t)N_DIM * K_DIM];     // fp16 weights
__device__ float g_scales[M_TOKENS];

// ---------------------------------------------------------------------------
// Kernel 0: pack int32-marshalled weights to fp16 (exact, |w| <= 127).
// ---------------------------------------------------------------------------
__global__ __launch_bounds__(256) void pack_w_kernel(const int* __restrict__ w32) {
    const int idx = blockIdx.x * blockDim.x + threadIdx.x;
    int4 v = reinterpret_cast<const int4*>(w32)[idx];
    __half2 h0 = __halves2half2(__int2half_rn(v.x), __int2half_rn(v.y));
    __half2 h1 = __halves2half2(__int2half_rn(v.z), __int2half_rn(v.w));
    uint2 hp = make_uint2(*(uint32_t*)&h0, *(uint32_t*)&h1);
    reinterpret_cast<uint2*>(g_wh)[idx] = hp;
}

// ---------------------------------------------------------------------------
// Kernel 1: per-token dynamic int8 quantization -> fp16 values (exact).
// ---------------------------------------------------------------------------
__global__ __launch_bounds__(256) void quant_kernel(const float* __restrict__ x) {
    const int token = blockIdx.x;
    const int tid = threadIdx.x;
    const int lane = tid & 31;
    const int warp = tid >> 5;

    const float4* xr = reinterpret_cast<const float4*>(x + (size_t)token * K_DIM);
    float4 v0 = xr[tid * 2 + 0];
    float4 v1 = xr[tid * 2 + 1];

    float m = fabsf(v0.x);
    m = fmaxf(m, fabsf(v0.y)); m = fmaxf(m, fabsf(v0.z)); m = fmaxf(m, fabsf(v0.w));
    m = fmaxf(m, fabsf(v1.x)); m = fmaxf(m, fabsf(v1.y));
    m = fmaxf(m, fabsf(v1.z)); m = fmaxf(m, fabsf(v1.w));

    #pragma unroll
    for (int off = 16; off > 0; off >>= 1)
        m = fmaxf(m, __shfl_xor_sync(0xFFFFFFFFu, m, off));

    __shared__ float wmax[8];
    if (lane == 0) wmax[warp] = m;
    __syncthreads();
    if (warp == 0) {
        float t = (lane < 8) ? wmax[lane] : 0.0f;
        #pragma unroll
        for (int off = 4; off > 0; off >>= 1)
            t = fmaxf(t, __shfl_xor_sync(0xFFFFFFFFu, t, off));
        if (lane == 0) wmax[0] = t;
    }
    __syncthreads();
    const float absmax = wmax[0];
    const float scale = fmaxf(absmax, EPS) / 127.0f;

    if (tid == 0) g_scales[token] = scale;

    const float inv = 1.0f / scale;
    float vals[8] = {v0.x, v0.y, v0.z, v0.w, v1.x, v1.y, v1.z, v1.w};
    int qv[8];
    #pragma unroll
    for (int i = 0; i < 8; i++) {
        float q = rintf(vals[i] * inv);
        q = fminf(fmaxf(q, -128.0f), 127.0f);
        qv[i] = (int)q;
    }
    uint4 hq;
    __half2 h;
    h = __halves2half2(__int2half_rn(qv[0]), __int2half_rn(qv[1])); hq.x = *(uint32_t*)&h;
    h = __halves2half2(__int2half_rn(qv[2]), __int2half_rn(qv[3])); hq.y = *(uint32_t*)&h;
    h = __halves2half2(__int2half_rn(qv[4]), __int2half_rn(qv[5])); hq.z = *(uint32_t*)&h;
    h = __halves2half2(__int2half_rn(qv[6]), __int2half_rn(qv[7])); hq.w = *(uint32_t*)&h;
    *reinterpret_cast<uint4*>(g_qh + (size_t)token * K_DIM + tid * 8) = hq;
}

// ---------------------------------------------------------------------------
// PTX helpers (TMA + mbarrier; patterns from validated examples)
// ---------------------------------------------------------------------------
__device__ __forceinline__ void mbar_init(uint32_t a, uint32_t cnt) {
    asm volatile("mbarrier.init.shared.b64 [%0], %1;" :: "r"(a), "r"(cnt) : "memory");
}
__device__ __forceinline__ void mbar_arrive(uint32_t a) {
    asm volatile("mbarrier.arrive.shared.b64 _, [%0];" :: "r"(a) : "memory");
}
__device__ __forceinline__ void mbar_expect_tx(uint32_t a, uint32_t bytes) {
    asm volatile("mbarrier.arrive.expect_tx.shared.b64 _, [%0], %1;" :: "r"(a), "r"(bytes) : "memory");
}
__device__ __forceinline__ void mbar_wait(uint32_t a, uint32_t parity) {
    asm volatile(
        "{\n\t.reg .pred P;\n"
        "W1_%=:\n\t"
        "mbarrier.try_wait.parity.acquire.cta.shared::cta.b64 P, [%0], %1, 0x989680;\n\t"
        "@P bra.uni W2_%=;\n\t"
        "bra.uni W1_%=;\n"
        "W2_%=:\n\t}"
        :: "r"(a), "r"(parity) : "memory");
}
__device__ __forceinline__ void tma3d(uint32_t smem, const CUtensorMap* map, int x, int y, uint32_t mbar) {
    asm volatile(
        "cp.async.bulk.tensor.3d.shared::cta.global.tile.mbarrier::complete_tx::bytes "
        "[%0], [%1, {%2, %3, %4}], [%5];"
        :: "r"(smem), "l"(map), "r"(x), "r"(y), "r"(0), "r"(mbar) : "memory");
}
__device__ __forceinline__ void ldsm4(uint32_t& r0, uint32_t& r1, uint32_t& r2, uint32_t& r3,
                                      uint32_t addr) {
    asm volatile("ldmatrix.sync.aligned.m8n8.x4.shared.b16 {%0,%1,%2,%3}, [%4];"
                 : "=r"(r0), "=r"(r1), "=r"(r2), "=r"(r3) : "r"(addr));
}

// ---------------------------------------------------------------------------
// Kernel 2: fp16 HMMA GEMM, TMA producer + mbarrier pipeline, SW128 smem,
// 128x128 tile, 2 CTAs/SM. Launched twice (half-M each) for ncu visibility.
// ---------------------------------------------------------------------------
__global__ __launch_bounds__(256, 2) void gemm_f16_kernel(
    const __grid_constant__ CUtensorMap tma_a,
    const __grid_constant__ CUtensorMap tma_b,
    const float* __restrict__ w_scale,
    const float* __restrict__ bias,
    float* __restrict__ out,
    int m_base)
{
    extern __shared__ char smem[];
    const uint32_t sb = (uint32_t)__cvta_generic_to_shared(smem);

    const int tid = threadIdx.x;
    const int lane = tid & 31;
    const int warp = tid >> 5;
    const int warpM = warp >> 2;   // 0..1 (64 rows)
    const int warpN = warp & 3;    // 0..3 (32 cols)
    const int g = lane >> 2;
    const int tg = lane & 3;

    const int m0 = m_base + blockIdx.y * BM;
    const int n0 = blockIdx.x * BN;

    if (tid == 0) {
        #pragma unroll
        for (int s = 0; s < NSTAGE; s++) {
            mbar_init(sb + FULL_BAR(s), 1);
            mbar_init(sb + EMPTY_BAR(s), 256);
        }
    }
    __syncthreads();

    // Producer prologue: thread 0 issues stages 0..NSTAGE-2.
    // (fresh empty barrier + producer phase 1 -> wait passes immediately)
    if (tid == 0) {
        #pragma unroll
        for (int s = 0; s < NSTAGE - 1; s++) {
            mbar_expect_tx(sb + FULL_BAR(s), STAGE_B);
            tma3d(sb + s * STAGE_B,         &tma_a, s * 128, m0, sb + FULL_BAR(s));
            tma3d(sb + s * STAGE_B + 16384, &tma_b, s * 128, n0, sb + FULL_BAR(s));
        }
    }

    float acc[4][4][4];
    #pragma unroll
    for (int mi = 0; mi < 4; mi++)
        #pragma unroll
        for (int ni = 0; ni < 4; ni++)
            #pragma unroll
            for (int r = 0; r < 4; r++) acc[mi][ni][r] = 0.0f;

    // ldmatrix lane rows (validated layout) + SW128 per-lane XOR masks.
    const int aRow = warpM * 64 + (lane & 7) + ((lane >> 3) & 1) * 8;   // + mi*16
    const int aKof = (lane >> 4) * 16;
    const int bRow = warpN * 32 + (lane >> 4) * 8 + (lane & 7);         // + j2*16
    const int bKof = ((lane >> 3) & 1) * 16;
    const int aXor = (aRow & 7) * 16;    // row*128 untouched in bits<7: mask = (row&7)<<4
    const int bXor = (bRow & 7) * 16;

    int pstage = NSTAGE - 1, pph = 1;    // producer cursor (after prologue)
    int cstage = 0, cph = 0;             // consumer cursor

    for (int kt = 0; kt < NKT; kt++) {
        // Producer: issue stage kt+NSTAGE-1
        const int pf = kt + NSTAGE - 1;
        if (tid == 0 && pf < NKT) {
            mbar_wait(sb + EMPTY_BAR(pstage), pph);
            mbar_expect_tx(sb + FULL_BAR(pstage), STAGE_B);
            tma3d(sb + pstage * STAGE_B,         &tma_a, pf * 128, m0, sb + FULL_BAR(pstage));
            tma3d(sb + pstage * STAGE_B + 16384, &tma_b, pf * 128, n0, sb + FULL_BAR(pstage));
            if (++pstage == NSTAGE) { pstage = 0; pph ^= 1; }
        }

        // Consumers: wait data, compute 4 ks-steps of K16.
        mbar_wait(sb + FULL_BAR(cstage), cph);
        const uint32_t aBase = sb + cstage * STAGE_B;
        const uint32_t bBase = aBase + 16384;

        #pragma unroll
        for (int ks = 0; ks < 4; ks++) {
            const int k0 = ks * 32;
            uint32_t afr[4][4];
            #pragma unroll
            for (int mi = 0; mi < 4; mi++) {
                const int row = aRow + mi * 16;
                ldsm4(afr[mi][0], afr[mi][1], afr[mi][2], afr[mi][3],
                      aBase + row * 128 + ((k0 + aKof) ^ aXor));
            }
            uint32_t bfr[4][2];
            #pragma unroll
            for (int j2 = 0; j2 < 2; j2++) {
                const int row = bRow + j2 * 16;
                uint32_t b0, b1, b2, b3;
                ldsm4(b0, b1, b2, b3, bBase + row * 128 + ((k0 + bKof) ^ bXor));
                bfr[2 * j2][0] = b0; bfr[2 * j2][1] = b1;
                bfr[2 * j2 + 1][0] = b2; bfr[2 * j2 + 1][1] = b3;
            }
            #pragma unroll
            for (int mi = 0; mi < 4; mi++)
                #pragma unroll
                for (int ni = 0; ni < 4; ni++) {
                    asm volatile(
                        "mma.sync.aligned.m16n8k16.row.col.f32.f16.f16.f32 "
                        "{%0,%1,%2,%3}, {%4,%5,%6,%7}, {%8,%9}, {%0,%1,%2,%3};\n"
                        : "+f"(acc[mi][ni][0]), "+f"(acc[mi][ni][1]),
                          "+f"(acc[mi][ni][2]), "+f"(acc[mi][ni][3])
                        : "r"(afr[mi][0]), "r"(afr[mi][1]), "r"(afr[mi][2]), "r"(afr[mi][3]),
                          "r"(bfr[ni][0]), "r"(bfr[ni][1]));
                }
        }

        mbar_arrive(sb + EMPTY_BAR(cstage));
        if (++cstage == NSTAGE) { cstage = 0; cph ^= 1; }
    }

    // Epilogue: dequant + bias, round through fp16, store fp32 (validated).
    #pragma unroll
    for (int mi = 0; mi < 4; mi++) {
        const int r0 = m0 + warpM * 64 + mi * 16 + g;
        const float s0 = g_scales[r0];
        const float s1 = g_scales[r0 + 8];
        #pragma unroll
        for (int ni = 0; ni < 4; ni++) {
            const int c = n0 + warpN * 32 + ni * 8 + tg * 2;
            const float w0 = w_scale[c], w1 = w_scale[c + 1];
            const float b0 = bias[c],    b1 = bias[c + 1];
            float2 o0, o1;
            o0.x = __half2float(__float2half_rn(acc[mi][ni][0] * s0 * w0 + b0));
            o0.y = __half2float(__float2half_rn(acc[mi][ni][1] * s0 * w1 + b1));
            o1.x = __half2float(__float2half_rn(acc[mi][ni][2] * s1 * w0 + b0));
            o1.y = __half2float(__float2half_rn(acc[mi][ni][3] * s1 * w1 + b1));
            *reinterpret_cast<float2*>(out + (size_t)r0 * N_DIM + c) = o0;
            *reinterpret_cast<float2*>(out + (size_t)(r0 + 8) * N_DIM + c) = o1;
        }
    }
}

// ---------------------------------------------------------------------------
// Host launcher
// ---------------------------------------------------------------------------
typedef CUresult (*PFN_encodeTiled)(
    CUtensorMap*, CUtensorMapDataType, cuuint32_t, void*,
    const cuuint64_t*, const cuuint64_t*, const cuuint32_t*, const cuuint32_t*,
    CUtensorMapInterleave, CUtensorMapSwizzle, CUtensorMapL2promotion,
    CUtensorMapFloatOOBfill);

extern "C" void kernel_launch(void* const* d_in, const int* in_sizes, int n_in,
                              void* d_out, int out_size) {
    const float* x       = (const float*)d_in[0];
    const int*   weight  = (const int*)d_in[1];   // int8 marshalled as int32
    const float* w_scale = (const float*)d_in[2];
    const float* bias    = (const float*)d_in[3];
    float* out = (float*)d_out;

    pack_w_kernel<<<(N_DIM * K_DIM / 4) / 256, 256>>>(weight);
    quant_kernel<<<M_TOKENS, 256>>>(x);

    void* qptr = nullptr;
    void* wptr = nullptr;
    cudaGetSymbolAddress(&qptr, g_qh);
    cudaGetSymbolAddress(&wptr, g_wh);

    PFN_encodeTiled enc = nullptr;
    cudaDriverEntryPointQueryResult qres;
    cudaGetDriverEntryPointByVersion("cuTensorMapEncodeTiled", (void**)&enc, 12000,
                                     cudaEnableDefault, &qres);

    // Byte-typed views of the fp16 matrices: dims {K bytes, rows, 1}, SW128.
    CUtensorMap ta, tb;
    cuuint64_t dimsA[3] = {K_DIM * 2, M_TOKENS, 1};
    cuuint64_t strA[2]  = {K_DIM * 2, (cuuint64_t)(K_DIM * 2) * M_TOKENS};
    cuuint64_t dimsB[3] = {K_DIM * 2, N_DIM, 1};
    cuuint64_t strB[2]  = {K_DIM * 2, (cuuint64_t)(K_DIM * 2) * N_DIM};
    cuuint32_t box[3]   = {128, 128, 1};
    cuuint32_t es[3]    = {1, 1, 1};

    enc(&ta, CU_TENSOR_MAP_DATA_TYPE_UINT8, 3, qptr, dimsA, strA, box, es,
        CU_TENSOR_MAP_INTERLEAVE_NONE, CU_TENSOR_MAP_SWIZZLE_128B,
        CU_TENSOR_MAP_L2_PROMOTION_L2_128B, CU_TENSOR_MAP_FLOAT_OOB_FILL_NONE);
    enc(&tb, CU_TENSOR_MAP_DATA_TYPE_UINT8, 3, wptr, dimsB, strB, box, es,
        CU_TENSOR_MAP_INTERLEAVE_NONE, CU_TENSOR_MAP_SWIZZLE_128B,
        CU_TENSOR_MAP_L2_PROMOTION_L2_128B, CU_TENSOR_MAP_FLOAT_OOB_FILL_NONE);

    cudaFuncSetAttribute(gemm_f16_kernel, cudaFuncAttributeMaxDynamicSharedMemorySize, SMEM_TOTAL);
    dim3 grid(N_DIM / BN, M_TOKENS / BM / 2);   // (16, 64) per half
    gemm_f16_kernel<<<grid, 256, SMEM_TOTAL>>>(ta, tb, w_scale, bias, out, 0);
    gemm_f16_kernel<<<grid, 256, SMEM_TOTAL>>>(ta, tb, w_scale, bias, out, M_TOKENS / 2);
}